// round 2
// baseline (speedup 1.0000x reference)
#include <cuda_runtime.h>
#include <cuda_bf16.h>
#include <cstddef>

// Problem constants
#define NN 100000      // nodes
#define NE 800000      // edges
#define HD 256         // hidden dim
#define NL 6           // layers
#define W1_LD 259      // H + 3 edge features
#define W2_LD 512      // H + INTER

// ---------------- scratch (device globals; no runtime allocation) ----------
__device__ float g_hA[(size_t)NN * HD];
__device__ float g_hB[(size_t)NN * HD];
__device__ float g_P [(size_t)NN * HD];
__device__ float g_hN[(size_t)NN * HD];
__device__ float g_deg[NN];
__device__ float g_invdeg[NN];

// ---------------- small elementwise kernels --------------------------------
__global__ void init_kernel(const int* __restrict__ gt,
                            const float* __restrict__ emb,
                            float* __restrict__ h,
                            float* __restrict__ deg) {
    int i = blockIdx.x * blockDim.x + threadIdx.x;
    if (i < NN * HD) {
        int node = i >> 8;
        int c    = i & 255;
        h[i] = emb[gt[node] * HD + c];
    }
    if (i < NN) deg[i] = 0.0f;
}

__global__ void deg_kernel(const int* __restrict__ dst, float* __restrict__ deg) {
    int e = blockIdx.x * blockDim.x + threadIdx.x;
    if (e < NE) atomicAdd(&deg[dst[e]], 1.0f);
}

__global__ void invdeg_kernel(const float* __restrict__ deg, float* __restrict__ inv) {
    int i = blockIdx.x * blockDim.x + threadIdx.x;
    if (i < NN) inv[i] = 1.0f / fmaxf(deg[i], 1.0f);
}

__global__ void zero_kernel(float* __restrict__ p, int n) {
    int i = blockIdx.x * blockDim.x + threadIdx.x;
    int stride = gridDim.x * blockDim.x;
    for (; i < n; i += stride) p[i] = 0.0f;
}

// ---------------- edge scatter: hN[dst] += leaky_relu(P[src] + w@W1b^T) ----
__global__ void edge_kernel(const int* __restrict__ src,
                            const int* __restrict__ dst,
                            const float* __restrict__ w,
                            const float* __restrict__ P,
                            const float* __restrict__ W1b,  // points at W1[l][0][256]
                            float* __restrict__ hN) {
    __shared__ float sW[3 * HD];   // sW[t*256 + c] = W1[l][c][256+t]
    for (int i = threadIdx.x; i < HD; i += blockDim.x) {
        sW[i]          = W1b[(size_t)i * W1_LD + 0];
        sW[HD + i]     = W1b[(size_t)i * W1_LD + 1];
        sW[2 * HD + i] = W1b[(size_t)i * W1_LD + 2];
    }
    __syncthreads();

    int warpId = (blockIdx.x * blockDim.x + threadIdx.x) >> 5;
    int lane   = threadIdx.x & 31;
    if (warpId >= NE) return;

    int s = src[warpId];
    int d = dst[warpId];
    float w0 = w[warpId * 3 + 0];
    float w1 = w[warpId * 3 + 1];
    float w2 = w[warpId * 3 + 2];

    const float* Ps  = P  + (size_t)s * HD;
    float*       out = hN + (size_t)d * HD;
#pragma unroll
    for (int j = 0; j < 8; j++) {
        int c = lane + j * 32;
        float v = Ps[c] + w0 * sW[c] + w1 * sW[HD + c] + w2 * sW[2 * HD + c];
        v = v > 0.0f ? v : 0.01f * v;  // leaky_relu 0.01
        atomicAdd(out + c, v);
    }
}

// ---------------- generic fp32 GEMM:  C = act(A1@B[:, :K1]^T (+ A2*rs @ B[:, K1:]^T) + bias)
// A1: [M, K1] row-major, A2: [M, K2] row-major (scaled by rowscale[m]), B rows with stride ldb.
#define BM 128
#define BN 128
#define BK 16

__global__ __launch_bounds__(256)
void gemm_kernel(const float* __restrict__ A1, int K1,
                 const float* __restrict__ A2, int K2,
                 const float* __restrict__ rowscale,
                 const float* __restrict__ B, int ldb,
                 const float* __restrict__ bias,
                 float* __restrict__ C, int M, int N, int act) {
    __shared__ float As[BK][BM];
    __shared__ float Bs[BK][BN + 4];

    int tid = threadIdx.x;
    int tx = tid & 15;
    int ty = tid >> 4;
    int mBase = blockIdx.y * BM;
    int nBase = blockIdx.x * BN;
    int K = K1 + K2;

    float acc[8][8];
#pragma unroll
    for (int i = 0; i < 8; i++)
#pragma unroll
        for (int j = 0; j < 8; j++) acc[i][j] = 0.0f;

    for (int kBase = 0; kBase < K; kBase += BK) {
        // A tile: [BM x BK] via float4, 2 per thread
#pragma unroll
        for (int i = 0; i < 2; i++) {
            int linear = tid + i * 256;          // 0..511
            int r  = linear >> 2;                // 0..127
            int c4 = (linear & 3) * 4;           // 0,4,8,12
            int row = mBase + r;
            int rc  = row < M ? row : (M - 1);
            int kg  = kBase + c4;
            float4 v;
            if (kg < K1) {
                v = *(const float4*)(A1 + (size_t)rc * K1 + kg);
            } else {
                v = *(const float4*)(A2 + (size_t)rc * K2 + (kg - K1));
                float sc = rowscale[rc];
                v.x *= sc; v.y *= sc; v.z *= sc; v.w *= sc;
            }
            As[c4 + 0][r] = v.x;
            As[c4 + 1][r] = v.y;
            As[c4 + 2][r] = v.z;
            As[c4 + 3][r] = v.w;
        }
        // B tile: [BN x BK] scalar (ldb may be odd, e.g. 259), 8 per thread
#pragma unroll
        for (int i = 0; i < 8; i++) {
            int linear = tid + i * 256;          // 0..2047
            int k = linear & 15;
            int r = linear >> 4;                 // 0..127
            Bs[k][r] = B[(size_t)(nBase + r) * ldb + kBase + k];
        }
        __syncthreads();

#pragma unroll
        for (int kk = 0; kk < BK; kk++) {
            float a[8], b[8];
#pragma unroll
            for (int i = 0; i < 8; i++) a[i] = As[kk][ty * 8 + i];
#pragma unroll
            for (int j = 0; j < 8; j++) b[j] = Bs[kk][tx * 8 + j];
#pragma unroll
            for (int i = 0; i < 8; i++)
#pragma unroll
                for (int j = 0; j < 8; j++)
                    acc[i][j] = fmaf(a[i], b[j], acc[i][j]);
        }
        __syncthreads();
    }

#pragma unroll
    for (int i = 0; i < 8; i++) {
        int row = mBase + ty * 8 + i;
        if (row >= M) continue;
#pragma unroll
        for (int j = 0; j < 8; j++) {
            int col = nBase + tx * 8 + j;
            float v = acc[i][j];
            if (bias) v += bias[col];
            if (act)  v = fmaxf(v, 0.0f);
            C[(size_t)row * N + col] = v;
        }
    }
}

// ---------------- head dot: out[n] = x[n] . Wh2 + bh2 ----------------------
__global__ void head_dot_kernel(const float* __restrict__ x,
                                const float* __restrict__ Wh2,
                                const float* __restrict__ bh2,
                                float* __restrict__ out) {
    int node = blockIdx.x * (blockDim.x >> 5) + (threadIdx.x >> 5);
    int lane = threadIdx.x & 31;
    if (node >= NN) return;
    const float* xr = x + (size_t)node * HD;
    float s = 0.0f;
#pragma unroll
    for (int j = 0; j < 8; j++) {
        int c = lane + j * 32;
        s = fmaf(xr[c], Wh2[c], s);
    }
#pragma unroll
    for (int off = 16; off; off >>= 1)
        s += __shfl_xor_sync(0xffffffffu, s, off);
    if (lane == 0) out[node] = s + bh2[0];
}

// ---------------- launch ---------------------------------------------------
extern "C" void kernel_launch(void* const* d_in, const int* in_sizes, int n_in,
                              void* d_out, int out_size) {
    const int*   gate_type = (const int*)  d_in[0];
    const int*   src       = (const int*)  d_in[1];
    const int*   dst       = (const int*)  d_in[2];
    const float* w         = (const float*)d_in[3];
    const float* emb       = (const float*)d_in[4];
    const float* W1        = (const float*)d_in[5];
    const float* W2        = (const float*)d_in[6];
    const float* b2        = (const float*)d_in[7];
    const float* Wh1       = (const float*)d_in[8];
    const float* bh1       = (const float*)d_in[9];
    const float* Wh2       = (const float*)d_in[10];
    const float* bh2       = (const float*)d_in[11];
    float* out = (float*)d_out;

    float *hA, *hB, *P, *hN, *deg, *invdeg;
    cudaGetSymbolAddress((void**)&hA,     g_hA);
    cudaGetSymbolAddress((void**)&hB,     g_hB);
    cudaGetSymbolAddress((void**)&P,      g_P);
    cudaGetSymbolAddress((void**)&hN,     g_hN);
    cudaGetSymbolAddress((void**)&deg,    g_deg);
    cudaGetSymbolAddress((void**)&invdeg, g_invdeg);

    // h0 = emb[gate_type]; deg = in-degree; invdeg = 1/max(deg,1)
    init_kernel<<<(NN * HD + 255) / 256, 256>>>(gate_type, emb, hA, deg);
    deg_kernel<<<(NE + 255) / 256, 256>>>(dst, deg);
    invdeg_kernel<<<(NN + 255) / 256, 256>>>(deg, invdeg);

    dim3 ggrid(HD / BN, (NN + BM - 1) / BM);   // (2, 782)
    float* hcur = hA;
    float* hnext = hB;

    for (int l = 0; l < NL; l++) {
        const float* W1l = W1 + (size_t)l * HD * W1_LD;
        const float* W2l = W2 + (size_t)l * HD * W2_LD;
        const float* b2l = b2 + (size_t)l * HD;

        // P = h @ W1[:, :256]^T   (node-space; avoids the 8x larger edge GEMM)
        gemm_kernel<<<ggrid, 256>>>(hcur, HD, nullptr, 0, nullptr,
                                    W1l, W1_LD, nullptr, P, NN, HD, 0);

        zero_kernel<<<2048, 256>>>(hN, NN * HD);

        // hN[dst] += leaky_relu(P[src] + w @ W1[:, 256:259]^T)
        edge_kernel<<<(NE * 32 + 255) / 256, 256>>>(src, dst, w, P, W1l + HD, hN);

        // h' = relu(h @ W2[:, :256]^T + (hN*invdeg) @ W2[:, 256:]^T + b2)
        gemm_kernel<<<ggrid, 256>>>(hcur, HD, hN, HD, invdeg,
                                    W2l, W2_LD, b2l, hnext, NN, HD, 1);

        float* t = hcur; hcur = hnext; hnext = t;
    }

    // head: x = relu(h @ Wh1^T + bh1); out = x @ Wh2^T + bh2
    gemm_kernel<<<ggrid, 256>>>(hcur, HD, nullptr, 0, nullptr,
                                Wh1, HD, bh1, P, NN, HD, 1);
    head_dot_kernel<<<(NN * 32 + 255) / 256, 256>>>(P, Wh2, bh2, out);
}

// round 4
// speedup vs baseline: 1.2801x; 1.2801x over previous
#include <cuda_runtime.h>
#include <cuda_bf16.h>
#include <cstdint>
#include <cstddef>

// Problem constants
#define NN 100000      // nodes
#define NE 800000      // edges
#define HD 256         // hidden dim
#define NL 6           // layers
#define W1_LD 259      // H + 3 edge features
#define W2_LD 512      // H + INTER

// ---------------- scratch (device globals; no runtime allocation) ----------
__device__ float g_hA[(size_t)NN * HD];
__device__ float g_hB[(size_t)NN * HD];
__device__ float g_P [(size_t)NN * HD];
__device__ float g_hN[(size_t)NN * HD];
__device__ float g_deg[NN];
__device__ float g_invdeg[NN];

__device__ __forceinline__ float tf32_rna(float a) {
    uint32_t b;
    asm("cvt.rna.tf32.f32 %0, %1;" : "=r"(b) : "f"(a));
    return __uint_as_float(b);
}

__device__ __forceinline__ void mma_tf32(float* c, const float* a, const float* b) {
    asm volatile(
        "mma.sync.aligned.m16n8k8.row.col.f32.tf32.tf32.f32 "
        "{%0,%1,%2,%3}, {%4,%5,%6,%7}, {%8,%9}, {%0,%1,%2,%3};"
        : "+f"(c[0]), "+f"(c[1]), "+f"(c[2]), "+f"(c[3])
        : "r"(__float_as_uint(a[0])), "r"(__float_as_uint(a[1])),
          "r"(__float_as_uint(a[2])), "r"(__float_as_uint(a[3])),
          "r"(__float_as_uint(b[0])), "r"(__float_as_uint(b[1])));
}

// ---------------- small elementwise kernels --------------------------------
__global__ void init_kernel(const int* __restrict__ gt,
                            const float* __restrict__ emb,
                            float* __restrict__ h,
                            float* __restrict__ deg) {
    int i = blockIdx.x * blockDim.x + threadIdx.x;
    if (i < NN * HD) {
        int node = i >> 8;
        int c    = i & 255;
        h[i] = emb[gt[node] * HD + c];
    }
    if (i < NN) deg[i] = 0.0f;
}

__global__ void deg_kernel(const int* __restrict__ dst, float* __restrict__ deg) {
    int e = blockIdx.x * blockDim.x + threadIdx.x;
    if (e < NE) atomicAdd(&deg[dst[e]], 1.0f);
}

__global__ void invdeg_kernel(const float* __restrict__ deg, float* __restrict__ inv) {
    int i = blockIdx.x * blockDim.x + threadIdx.x;
    if (i < NN) inv[i] = 1.0f / fmaxf(deg[i], 1.0f);
}

__global__ void zero_kernel(float* __restrict__ p, int n) {
    int i = blockIdx.x * blockDim.x + threadIdx.x;
    int stride = gridDim.x * blockDim.x;
    for (; i < n; i += stride) p[i] = 0.0f;
}

// ---------------- edge scatter: hN[dst] += leaky_relu(P[src] + w@W1b^T) ----
__global__ void edge_kernel(const int* __restrict__ src,
                            const int* __restrict__ dst,
                            const float* __restrict__ w,
                            const float* __restrict__ P,
                            const float* __restrict__ W1b,  // points at W1[l][0][256]
                            float* __restrict__ hN) {
    __shared__ float sW[3 * HD];   // sW[t*256 + c] = W1[l][c][256+t]
    for (int i = threadIdx.x; i < HD; i += blockDim.x) {
        sW[i]          = W1b[(size_t)i * W1_LD + 0];
        sW[HD + i]     = W1b[(size_t)i * W1_LD + 1];
        sW[2 * HD + i] = W1b[(size_t)i * W1_LD + 2];
    }
    __syncthreads();

    int warpId = (blockIdx.x * blockDim.x + threadIdx.x) >> 5;
    int lane   = threadIdx.x & 31;
    if (warpId >= NE) return;

    int s = src[warpId];
    int d = dst[warpId];
    float w0 = w[warpId * 3 + 0];
    float w1 = w[warpId * 3 + 1];
    float w2 = w[warpId * 3 + 2];

    const float* Ps  = P  + (size_t)s * HD;
    float*       out = hN + (size_t)d * HD;
#pragma unroll
    for (int j = 0; j < 8; j++) {
        int c = lane + j * 32;
        float v = Ps[c] + w0 * sW[c] + w1 * sW[HD + c] + w2 * sW[2 * HD + c];
        v = v > 0.0f ? v : 0.01f * v;  // leaky_relu 0.01
        atomicAdd(out + c, v);
    }
}

// ---------------- tensor-core tf32 GEMM (mma.sync, 3-term split) -----------
// C[M rows, N cols] tile BM x BN = act( A1 @ B[:, :K1]^T + (A2*rowscale) @ B[:, K1:]^T + bias )
// A1: [M, K1] row-major, A2: [M, K2] row-major, B rows stride ldb (output-col major).
#define BM 128
#define BN 64
#define KC 16
#define SSTR 20   // smem row stride (floats); conflict-free fragment pattern

__global__ __launch_bounds__(256)
void mma_gemm_kernel(const float* __restrict__ A1, int K1,
                     const float* __restrict__ A2, int K2,
                     const float* __restrict__ rowscale,
                     const float* __restrict__ B, int ldb,
                     const float* __restrict__ bias,
                     float* __restrict__ C, int M, int N, int act) {
    __shared__ float Ah[BM * SSTR];
    __shared__ float Al[BM * SSTR];
    __shared__ float Bh[BN * SSTR];
    __shared__ float Bl[BN * SSTR];

    int tid  = threadIdx.x;
    int wid  = tid >> 5;
    int lane = tid & 31;
    int grp  = lane >> 2;   // 0..7
    int tg   = lane & 3;    // 0..3
    int warp_m = wid & 3;   // 4 warps along M
    int warp_n = wid >> 2;  // 2 warps along N
    int m0 = warp_m * 32;
    int n0 = warp_n * 32;
    int mBase = blockIdx.y * BM;
    int nBase = blockIdx.x * BN;

    float acc[2][4][4];
#pragma unroll
    for (int i = 0; i < 2; i++)
#pragma unroll
        for (int j = 0; j < 4; j++)
#pragma unroll
            for (int q = 0; q < 4; q++) acc[i][j][q] = 0.0f;

    int K = K1 + K2;
    int nch = K / KC;
    int k1ch = K1 / KC;

    for (int kc = 0; kc < nch; kc++) {
        int kBase = kc * KC;
        bool useA2 = (kc >= k1ch);
        const float* Asrc = useA2 ? A2 : A1;
        int Ak  = useA2 ? (kBase - K1) : kBase;
        int Kld = useA2 ? K2 : K1;

        // A chunk: 128 x 16 floats = 512 float4 jobs, 2 per thread
#pragma unroll
        for (int i = 0; i < 2; i++) {
            int job = tid + i * 256;
            int r  = job >> 2;
            int c4 = (job & 3) * 4;
            int row = mBase + r;
            if (row >= M) row = M - 1;
            float4 v = *(const float4*)(Asrc + (size_t)row * Kld + Ak + c4);
            if (useA2) {
                float sc = rowscale[row];
                v.x *= sc; v.y *= sc; v.z *= sc; v.w *= sc;
            }
            float4 hi, lo;
            hi.x = tf32_rna(v.x); lo.x = tf32_rna(v.x - hi.x);
            hi.y = tf32_rna(v.y); lo.y = tf32_rna(v.y - hi.y);
            hi.z = tf32_rna(v.z); lo.z = tf32_rna(v.z - hi.z);
            hi.w = tf32_rna(v.w); lo.w = tf32_rna(v.w - hi.w);
            *(float4*)(Ah + r * SSTR + c4) = hi;
            *(float4*)(Al + r * SSTR + c4) = lo;
        }
        // B chunk: 64 x 16 floats = 1024 scalar jobs, 4 per thread (ldb may be odd)
#pragma unroll
        for (int i = 0; i < 4; i++) {
            int job = tid + i * 256;
            int nrow = job >> 4;
            int k = job & 15;
            float v = B[(size_t)(nBase + nrow) * ldb + kBase + k];
            float hi = tf32_rna(v);
            float lo = tf32_rna(v - hi);
            Bh[nrow * SSTR + k] = hi;
            Bl[nrow * SSTR + k] = lo;
        }
        __syncthreads();

#pragma unroll
        for (int ks = 0; ks < 2; ks++) {
            int kcol = ks * 8 + tg;
            float ah[2][4], al[2][4], bh[4][2], bl[4][2];
#pragma unroll
            for (int mt = 0; mt < 2; mt++) {
                int r = m0 + mt * 16 + grp;
                ah[mt][0] = Ah[r * SSTR + kcol];
                ah[mt][1] = Ah[(r + 8) * SSTR + kcol];
                ah[mt][2] = Ah[r * SSTR + kcol + 4];
                ah[mt][3] = Ah[(r + 8) * SSTR + kcol + 4];
                al[mt][0] = Al[r * SSTR + kcol];
                al[mt][1] = Al[(r + 8) * SSTR + kcol];
                al[mt][2] = Al[r * SSTR + kcol + 4];
                al[mt][3] = Al[(r + 8) * SSTR + kcol + 4];
            }
#pragma unroll
            for (int nt = 0; nt < 4; nt++) {
                int nr = n0 + nt * 8 + grp;
                bh[nt][0] = Bh[nr * SSTR + kcol];
                bh[nt][1] = Bh[nr * SSTR + kcol + 4];
                bl[nt][0] = Bl[nr * SSTR + kcol];
                bl[nt][1] = Bl[nr * SSTR + kcol + 4];
            }
#pragma unroll
            for (int mt = 0; mt < 2; mt++)
#pragma unroll
                for (int nt = 0; nt < 4; nt++) {
                    mma_tf32(acc[mt][nt], ah[mt], bh[nt]);
                    mma_tf32(acc[mt][nt], al[mt], bh[nt]);
                    mma_tf32(acc[mt][nt], ah[mt], bl[nt]);
                }
        }
        __syncthreads();
    }

    // Epilogue
#pragma unroll
    for (int mt = 0; mt < 2; mt++) {
        int row0 = mBase + m0 + mt * 16 + grp;
#pragma unroll
        for (int half = 0; half < 2; half++) {
            int row = row0 + half * 8;
            if (row >= M) continue;
#pragma unroll
            for (int nt = 0; nt < 4; nt++) {
                int col = nBase + n0 + nt * 8 + 2 * tg;
                float2 v;
                v.x = acc[mt][nt][half * 2 + 0];
                v.y = acc[mt][nt][half * 2 + 1];
                if (bias) { v.x += bias[col]; v.y += bias[col + 1]; }
                if (act)  { v.x = fmaxf(v.x, 0.0f); v.y = fmaxf(v.y, 0.0f); }
                *(float2*)(C + (size_t)row * N + col) = v;
            }
        }
    }
}

// ---------------- head dot: out[n] = x[n] . Wh2 + bh2 ----------------------
__global__ void head_dot_kernel(const float* __restrict__ x,
                                const float* __restrict__ Wh2,
                                const float* __restrict__ bh2,
                                float* __restrict__ out) {
    int node = blockIdx.x * (blockDim.x >> 5) + (threadIdx.x >> 5);
    int lane = threadIdx.x & 31;
    if (node >= NN) return;
    const float* xr = x + (size_t)node * HD;
    float s = 0.0f;
#pragma unroll
    for (int j = 0; j < 8; j++) {
        int c = lane + j * 32;
        s = fmaf(xr[c], Wh2[c], s);
    }
#pragma unroll
    for (int off = 16; off; off >>= 1)
        s += __shfl_xor_sync(0xffffffffu, s, off);
    if (lane == 0) out[node] = s + bh2[0];
}

// ---------------- launch ---------------------------------------------------
extern "C" void kernel_launch(void* const* d_in, const int* in_sizes, int n_in,
                              void* d_out, int out_size) {
    const int*   gate_type = (const int*)  d_in[0];
    const int*   src       = (const int*)  d_in[1];
    const int*   dst       = (const int*)  d_in[2];
    const float* w         = (const float*)d_in[3];
    const float* emb       = (const float*)d_in[4];
    const float* W1        = (const float*)d_in[5];
    const float* W2        = (const float*)d_in[6];
    const float* b2        = (const float*)d_in[7];
    const float* Wh1       = (const float*)d_in[8];
    const float* bh1       = (const float*)d_in[9];
    const float* Wh2       = (const float*)d_in[10];
    const float* bh2       = (const float*)d_in[11];
    float* out = (float*)d_out;

    float *hA, *hB, *P, *hN, *deg, *invdeg;
    cudaGetSymbolAddress((void**)&hA,     g_hA);
    cudaGetSymbolAddress((void**)&hB,     g_hB);
    cudaGetSymbolAddress((void**)&P,      g_P);
    cudaGetSymbolAddress((void**)&hN,     g_hN);
    cudaGetSymbolAddress((void**)&deg,    g_deg);
    cudaGetSymbolAddress((void**)&invdeg, g_invdeg);

    // h0 = emb[gate_type]; deg = in-degree; invdeg = 1/max(deg,1)
    init_kernel<<<(NN * HD + 255) / 256, 256>>>(gate_type, emb, hA, deg);
    deg_kernel<<<(NE + 255) / 256, 256>>>(dst, deg);
    invdeg_kernel<<<(NN + 255) / 256, 256>>>(deg, invdeg);

    dim3 ggrid(HD / BN, (NN + BM - 1) / BM);   // (4, 782)
    float* hcur = hA;
    float* hnext = hB;

    for (int l = 0; l < NL; l++) {
        const float* W1l = W1 + (size_t)l * HD * W1_LD;
        const float* W2l = W2 + (size_t)l * HD * W2_LD;
        const float* b2l = b2 + (size_t)l * HD;

        // P = h @ W1[:, :256]^T   (node-space; avoids the 8x larger edge GEMM)
        mma_gemm_kernel<<<ggrid, 256>>>(hcur, HD, nullptr, 0, nullptr,
                                        W1l, W1_LD, nullptr, P, NN, HD, 0);

        zero_kernel<<<2048, 256>>>(hN, NN * HD);

        // hN[dst] += leaky_relu(P[src] + w @ W1[:, 256:259]^T)
        edge_kernel<<<(NE * 32 + 255) / 256, 256>>>(src, dst, w, P, W1l + HD, hN);

        // h' = relu(h @ W2[:, :256]^T + (hN*invdeg) @ W2[:, 256:]^T + b2)
        mma_gemm_kernel<<<ggrid, 256>>>(hcur, HD, hN, HD, invdeg,
                                        W2l, W2_LD, b2l, hnext, NN, HD, 1);

        float* t = hcur; hcur = hnext; hnext = t;
    }

    // head: x = relu(h @ Wh1^T + bh1); out = x @ Wh2^T + bh2
    mma_gemm_kernel<<<ggrid, 256>>>(hcur, HD, nullptr, 0, nullptr,
                                    Wh1, HD, bh1, P, NN, HD, 1);
    head_dot_kernel<<<(NN * 32 + 255) / 256, 256>>>(P, Wh2, bh2, out);
}